// round 9
// baseline (speedup 1.0000x reference)
#include <cuda_runtime.h>
#include <math.h>
#include <stdint.h>

// Problem constants
#define B_    2
#define T_    2048
#define H_    1024
#define NH_   16
#define HD_   64
#define WIN_  256

// Scratch (device globals — allocation-free per harness rules)
__device__ float g_qkv[(size_t)B_ * T_ * 3 * H_];   // [B,T,3H]
__device__ float g_att[(size_t)B_ * T_ * H_];       // [B,T,H] attn out (tf32-rounded)
__device__ float g_x[(size_t)B_ * T_ * H_];         // tf32-rounded x
__device__ float g_wqkv[(size_t)H_ * 3 * H_];       // tf32-rounded W_qkv
__device__ float g_wout[(size_t)H_ * H_];           // tf32-rounded W_out

__device__ __forceinline__ float f2tf32(float x) {
    uint32_t u;
    asm("cvt.rna.tf32.f32 %0, %1;" : "=r"(u) : "f"(x));
    return __uint_as_float(u);
}

__device__ __forceinline__ void mma_tf32(float c[4], const uint32_t a[4], const uint32_t b[2]) {
    asm volatile(
        "mma.sync.aligned.m16n8k8.row.col.f32.tf32.tf32.f32 "
        "{%0,%1,%2,%3}, {%4,%5,%6,%7}, {%8,%9}, {%0,%1,%2,%3};"
        : "+f"(c[0]), "+f"(c[1]), "+f"(c[2]), "+f"(c[3])
        : "r"(a[0]), "r"(a[1]), "r"(a[2]), "r"(a[3]), "r"(b[0]), "r"(b[1]));
}

__device__ __forceinline__ void cp_async16(float* smem_dst, const float* gsrc) {
    uint32_t s = (uint32_t)__cvta_generic_to_shared(smem_dst);
    asm volatile("cp.async.cg.shared.global [%0], [%1], 16;" :: "r"(s), "l"(gsrc));
}
__device__ __forceinline__ void cp_commit() {
    asm volatile("cp.async.commit_group;");
}
template <int N>
__device__ __forceinline__ void cp_wait() {
    asm volatile("cp.async.wait_group %0;" :: "n"(N));
}

// ---------------------------------------------------------------------------
// Prepass: elementwise tf32 rounding (rna) of GEMM operands.
// ---------------------------------------------------------------------------
__global__ void round_tf32_kernel(const float* __restrict__ src,
                                  float* __restrict__ dst, int n4)
{
    const int i = blockIdx.x * blockDim.x + threadIdx.x;
    if (i < n4) {
        float4 v = ((const float4*)src)[i];
        v.x = f2tf32(v.x);
        v.y = f2tf32(v.y);
        v.z = f2tf32(v.z);
        v.w = f2tf32(v.w);
        ((float4*)dst)[i] = v;
    }
}

// ---------------------------------------------------------------------------
// TF32 tensor-core GEMM, cp.async double buffering. Inputs ALREADY tf32-
// rounded in global memory -> mainloop is pure LDS + MMA (no cvt).
// C[M,N] = A[M,K] @ Bm[K,N] + bias[N]
// 128x128 block tile, BK=32, 256 threads = 8 warps (2x4), warp tile 64x32.
// ---------------------------------------------------------------------------
#define BM 128
#define BN 128
#define BK 32
#define AS_STRIDE 36
#define BS_STRIDE 136
#define STAGE_FLOATS (BM * AS_STRIDE + BK * BS_STRIDE)   // 8960
#define GEMM_SMEM (2 * STAGE_FLOATS * 4)                 // 71680 B

__global__ __launch_bounds__(256, 2)
void gemm_tf32_bias(const float* __restrict__ A, const float* __restrict__ Bm,
                    const float* __restrict__ bias, float* __restrict__ C,
                    int M, int N, int K)
{
    extern __shared__ float smem[];

    const int tid  = threadIdx.x;
    const int wid  = tid >> 5;
    const int lane = tid & 31;
    const int wm   = wid >> 2;
    const int wn   = wid & 3;
    const int grp  = lane >> 2;
    const int qid  = lane & 3;

    const float* Ab = A  + (size_t)(blockIdx.y * BM) * K;
    const float* Bb = Bm + (size_t)(blockIdx.x * BN);

    float acc[4][4][4];
#pragma unroll
    for (int m = 0; m < 4; m++)
#pragma unroll
        for (int n = 0; n < 4; n++)
#pragma unroll
            for (int r = 0; r < 4; r++) acc[m][n][r] = 0.f;

    const int ITER = K / BK;

    auto load_stage = [&](int k0, int s) {
        float* As = smem + s * STAGE_FLOATS;
        float* Bs = As + BM * AS_STRIDE;
#pragma unroll
        for (int i = 0; i < 4; i++) {
            const int flat = tid + i * 256;
            const int r  = flat >> 3;
            const int c4 = (flat & 7) * 4;
            cp_async16(As + r * AS_STRIDE + c4, Ab + (size_t)r * K + k0 + c4);
        }
#pragma unroll
        for (int i = 0; i < 4; i++) {
            const int flat = tid + i * 256;
            const int r  = flat >> 5;
            const int c4 = (flat & 31) * 4;
            cp_async16(Bs + r * BS_STRIDE + c4, Bb + (size_t)(k0 + r) * N + c4);
        }
        cp_commit();
    };

    load_stage(0, 0);

    for (int it = 0; it < ITER; it++) {
        if (it + 1 < ITER) {
            load_stage((it + 1) * BK, (it + 1) & 1);
            cp_wait<1>();
        } else {
            cp_wait<0>();
        }
        __syncthreads();

        const float* As = smem + (it & 1) * STAGE_FLOATS;
        const float* Bs = As + BM * AS_STRIDE;

#pragma unroll
        for (int ks = 0; ks < BK / 8; ks++) {
            const int kb = ks * 8;
            uint32_t af[4][4], bf[4][2];
#pragma unroll
            for (int m = 0; m < 4; m++) {
                const int r = wm * 64 + m * 16;
                af[m][0] = __float_as_uint(As[(r + grp    ) * AS_STRIDE + kb + qid    ]);
                af[m][1] = __float_as_uint(As[(r + grp + 8) * AS_STRIDE + kb + qid    ]);
                af[m][2] = __float_as_uint(As[(r + grp    ) * AS_STRIDE + kb + qid + 4]);
                af[m][3] = __float_as_uint(As[(r + grp + 8) * AS_STRIDE + kb + qid + 4]);
            }
#pragma unroll
            for (int n = 0; n < 4; n++) {
                const int c = wn * 32 + n * 8 + grp;
                bf[n][0] = __float_as_uint(Bs[(kb + qid    ) * BS_STRIDE + c]);
                bf[n][1] = __float_as_uint(Bs[(kb + qid + 4) * BS_STRIDE + c]);
            }
#pragma unroll
            for (int m = 0; m < 4; m++)
#pragma unroll
                for (int n = 0; n < 4; n++)
                    mma_tf32(acc[m][n], af[m], bf[n]);
        }
        __syncthreads();
    }

#pragma unroll
    for (int m = 0; m < 4; m++) {
        const int row0 = blockIdx.y * BM + wm * 64 + m * 16 + grp;
#pragma unroll
        for (int n = 0; n < 4; n++) {
            const int col = blockIdx.x * BN + wn * 32 + n * 8 + qid * 2;
            const float b0 = bias[col], b1 = bias[col + 1];
            float2 v0 = make_float2(acc[m][n][0] + b0, acc[m][n][1] + b1);
            float2 v1 = make_float2(acc[m][n][2] + b0, acc[m][n][3] + b1);
            *(float2*)(C + (size_t)row0 * N + col)       = v0;
            *(float2*)(C + (size_t)(row0 + 8) * N + col) = v1;
        }
    }
}

// ---------------------------------------------------------------------------
// Banded causal attention on tensor cores (tf32 mma, flash online softmax).
// Epilogue now writes tf32-rounded output so GEMM2 needs no cvt.
// ---------------------------------------------------------------------------
#define ATTN_SMEM2 ((64*68*3 + 64*72) * 4)

__global__ __launch_bounds__(128)
void attn_mma_kernel(float* __restrict__ out)
{
    extern __shared__ float sm[];
    float* Qs = sm;                   // [64][68]
    float* Ps = Qs + 64 * 68;         // [64][68]
    float* Ks = Ps + 64 * 68;         // [64][68]
    float* Vs = Ks + 64 * 68;         // [64][72]

    const int qt  = blockIdx.x;
    const int h   = blockIdx.y;
    const int b   = blockIdx.z;
    const int tid = threadIdx.x;
    const int wid  = tid >> 5;
    const int lane = tid & 31;
    const int g = lane >> 2;
    const int q = lane & 3;
    const int r0 = wid * 16;

    const size_t rs = 3 * H_;
    const size_t base_bt = (size_t)b * T_ * rs + (size_t)h * HD_;
    const size_t qbase = base_bt + (size_t)(qt * 64) * rs;

#pragma unroll
    for (int it = 0; it < 8; it++) {
        const int idx = tid + it * 128;
        const int i = idx >> 4, d4 = (idx & 15) << 2;
        float4 v = *(const float4*)&g_qkv[qbase + (size_t)i * rs + d4];
        float4 w;
        w.x = f2tf32(v.x * 0.125f);
        w.y = f2tf32(v.y * 0.125f);
        w.z = f2tf32(v.z * 0.125f);
        w.w = f2tf32(v.w * 0.125f);
        *(float4*)&Qs[i * 68 + d4] = w;
    }

    float oc[8][4];
#pragma unroll
    for (int nt = 0; nt < 8; nt++)
#pragma unroll
        for (int r = 0; r < 4; r++) oc[nt][r] = 0.f;

    float m0 = -1e30f, m1 = -1e30f, l0 = 0.f, l1 = 0.f;

    int kt0 = qt - 4; if (kt0 < 0) kt0 = 0;

    for (int kt = kt0; kt <= qt; kt++) {
        __syncthreads();

        const size_t kbase = base_bt + (size_t)(kt * 64) * rs + H_;
#pragma unroll
        for (int it = 0; it < 8; it++) {
            const int idx = tid + it * 128;
            const int j = idx >> 4, d4 = (idx & 15) << 2;
            float4 kv = *(const float4*)&g_qkv[kbase + (size_t)j * rs + d4];
            float4 vv = *(const float4*)&g_qkv[kbase + H_ + (size_t)j * rs + d4];
            float4 kw, vw;
            kw.x = f2tf32(kv.x); kw.y = f2tf32(kv.y); kw.z = f2tf32(kv.z); kw.w = f2tf32(kv.w);
            vw.x = f2tf32(vv.x); vw.y = f2tf32(vv.y); vw.z = f2tf32(vv.z); vw.w = f2tf32(vv.w);
            *(float4*)&Ks[j * 68 + d4] = kw;
            *(float4*)&Vs[j * 72 + d4] = vw;
        }
        __syncthreads();

        float s[8][4];
#pragma unroll
        for (int nt = 0; nt < 8; nt++)
#pragma unroll
            for (int r = 0; r < 4; r++) s[nt][r] = 0.f;

#pragma unroll
        for (int ks = 0; ks < 8; ks++) {
            const int kb = ks * 8;
            uint32_t a[4];
            a[0] = __float_as_uint(Qs[(r0 + g    ) * 68 + kb + q    ]);
            a[1] = __float_as_uint(Qs[(r0 + g + 8) * 68 + kb + q    ]);
            a[2] = __float_as_uint(Qs[(r0 + g    ) * 68 + kb + q + 4]);
            a[3] = __float_as_uint(Qs[(r0 + g + 8) * 68 + kb + q + 4]);
#pragma unroll
            for (int nt = 0; nt < 8; nt++) {
                uint32_t bb[2];
                bb[0] = __float_as_uint(Ks[(nt * 8 + g) * 68 + kb + q    ]);
                bb[1] = __float_as_uint(Ks[(nt * 8 + g) * 68 + kb + q + 4]);
                mma_tf32(s[nt], a, bb);
            }
        }

        const int ig0 = qt * 64 + r0 + g;
        const int ig1 = ig0 + 8;
#pragma unroll
        for (int nt = 0; nt < 8; nt++) {
            const int jg = kt * 64 + nt * 8 + 2 * q;
            int d00 = ig0 - jg;     if (d00 < 0 || d00 >= WIN_) s[nt][0] = -1e30f;
            int d01 = ig0 - jg - 1; if (d01 < 0 || d01 >= WIN_) s[nt][1] = -1e30f;
            int d10 = ig1 - jg;     if (d10 < 0 || d10 >= WIN_) s[nt][2] = -1e30f;
            int d11 = ig1 - jg - 1; if (d11 < 0 || d11 >= WIN_) s[nt][3] = -1e30f;
        }
        float mx0 = -1e30f, mx1 = -1e30f;
#pragma unroll
        for (int nt = 0; nt < 8; nt++) {
            mx0 = fmaxf(mx0, fmaxf(s[nt][0], s[nt][1]));
            mx1 = fmaxf(mx1, fmaxf(s[nt][2], s[nt][3]));
        }
        mx0 = fmaxf(mx0, __shfl_xor_sync(0xffffffffu, mx0, 1));
        mx0 = fmaxf(mx0, __shfl_xor_sync(0xffffffffu, mx0, 2));
        mx1 = fmaxf(mx1, __shfl_xor_sync(0xffffffffu, mx1, 1));
        mx1 = fmaxf(mx1, __shfl_xor_sync(0xffffffffu, mx1, 2));

        const float mn0 = fmaxf(m0, mx0), mn1 = fmaxf(m1, mx1);
        const float e0 = __expf(m0 - mn0), e1 = __expf(m1 - mn1);
        float rs0 = 0.f, rs1 = 0.f;
#pragma unroll
        for (int nt = 0; nt < 8; nt++) {
            const float p00 = __expf(s[nt][0] - mn0);
            const float p01 = __expf(s[nt][1] - mn0);
            const float p10 = __expf(s[nt][2] - mn1);
            const float p11 = __expf(s[nt][3] - mn1);
            rs0 += p00 + p01;
            rs1 += p10 + p11;
            float2 v0 = make_float2(f2tf32(p00), f2tf32(p01));
            float2 v1 = make_float2(f2tf32(p10), f2tf32(p11));
            *(float2*)&Ps[(r0 + g    ) * 68 + nt * 8 + 2 * q] = v0;
            *(float2*)&Ps[(r0 + g + 8) * 68 + nt * 8 + 2 * q] = v1;
        }
        rs0 += __shfl_xor_sync(0xffffffffu, rs0, 1);
        rs0 += __shfl_xor_sync(0xffffffffu, rs0, 2);
        rs1 += __shfl_xor_sync(0xffffffffu, rs1, 1);
        rs1 += __shfl_xor_sync(0xffffffffu, rs1, 2);

        l0 = l0 * e0 + rs0;  m0 = mn0;
        l1 = l1 * e1 + rs1;  m1 = mn1;

#pragma unroll
        for (int nt = 0; nt < 8; nt++) {
            oc[nt][0] *= e0; oc[nt][1] *= e0;
            oc[nt][2] *= e1; oc[nt][3] *= e1;
        }
        __syncthreads();

#pragma unroll
        for (int ks = 0; ks < 8; ks++) {
            const int kb = ks * 8;
            uint32_t a[4];
            a[0] = __float_as_uint(Ps[(r0 + g    ) * 68 + kb + q    ]);
            a[1] = __float_as_uint(Ps[(r0 + g + 8) * 68 + kb + q    ]);
            a[2] = __float_as_uint(Ps[(r0 + g    ) * 68 + kb + q + 4]);
            a[3] = __float_as_uint(Ps[(r0 + g + 8) * 68 + kb + q + 4]);
#pragma unroll
            for (int nt = 0; nt < 8; nt++) {
                uint32_t bb[2];
                bb[0] = __float_as_uint(Vs[(kb + q    ) * 72 + nt * 8 + g]);
                bb[1] = __float_as_uint(Vs[(kb + q + 4) * 72 + nt * 8 + g]);
                mma_tf32(oc[nt], a, bb);
            }
        }
    }

    // normalize + tf32-round + write (GEMM2 A operand needs no cvt)
    const float inv0 = 1.f / l0, inv1 = 1.f / l1;
    const int row0g = qt * 64 + r0 + g;
#pragma unroll
    for (int nt = 0; nt < 8; nt++) {
        const int col = h * HD_ + nt * 8 + 2 * q;
        float2 v0 = make_float2(f2tf32(oc[nt][0] * inv0), f2tf32(oc[nt][1] * inv0));
        float2 v1 = make_float2(f2tf32(oc[nt][2] * inv1), f2tf32(oc[nt][3] * inv1));
        *(float2*)&out[(size_t)(b * T_ + row0g    ) * H_ + col] = v0;
        *(float2*)&out[(size_t)(b * T_ + row0g + 8) * H_ + col] = v1;
    }
}

// ---------------------------------------------------------------------------
// Launch: round prepass -> qkv GEMM -> attention (mma) -> out GEMM
// ---------------------------------------------------------------------------
extern "C" void kernel_launch(void* const* d_in, const int* in_sizes, int n_in,
                              void* d_out, int out_size)
{
    const float* x     = (const float*)d_in[0];
    const float* W_qkv = (const float*)d_in[1];
    const float* b_qkv = (const float*)d_in[2];
    const float* W_out = (const float*)d_in[3];
    const float* b_out = (const float*)d_in[4];
    float* out = (float*)d_out;

    float* qkv;  cudaGetSymbolAddress((void**)&qkv,  g_qkv);
    float* att;  cudaGetSymbolAddress((void**)&att,  g_att);
    float* xr;   cudaGetSymbolAddress((void**)&xr,   g_x);
    float* wq;   cudaGetSymbolAddress((void**)&wq,   g_wqkv);
    float* wo;   cudaGetSymbolAddress((void**)&wo,   g_wout);

    const int M = B_ * T_;

    // 0) tf32 rounding prepass
    {
        const int nx = (B_ * T_ * H_) / 4;
        round_tf32_kernel<<<(nx + 255) / 256, 256>>>(x, xr, nx);
        const int nq = (H_ * 3 * H_) / 4;
        round_tf32_kernel<<<(nq + 255) / 256, 256>>>(W_qkv, wq, nq);
        const int no = (H_ * H_) / 4;
        round_tf32_kernel<<<(no + 255) / 256, 256>>>(W_out, wo, no);
    }

    cudaFuncSetAttribute(gemm_tf32_bias,
                         cudaFuncAttributeMaxDynamicSharedMemorySize, GEMM_SMEM);
    // 1) QKV projection
    {
        dim3 grid((3 * H_) / BN, M / BM);
        gemm_tf32_bias<<<grid, 256, GEMM_SMEM>>>(xr, wq, b_qkv, qkv, M, 3 * H_, H_);
    }
    // 2) Banded attention
    {
        cudaFuncSetAttribute(attn_mma_kernel,
                             cudaFuncAttributeMaxDynamicSharedMemorySize, ATTN_SMEM2);
        dim3 grid(T_ / 64, NH_, B_);
        attn_mma_kernel<<<grid, 128, ATTN_SMEM2>>>(att);
    }
    // 3) Output projection
    {
        dim3 grid(H_ / BN, M / BM);
        gemm_tf32_bias<<<grid, 256, GEMM_SMEM>>>(att, wo, b_out, out, M, H_, H_);
    }
}

// round 11
// speedup vs baseline: 1.0262x; 1.0262x over previous
#include <cuda_runtime.h>
#include <math.h>
#include <stdint.h>

// Problem constants
#define B_    2
#define T_    2048
#define H_    1024
#define NH_   16
#define HD_   64
#define WIN_  256

// Scratch (device globals — allocation-free per harness rules)
__device__ float g_qkv[(size_t)B_ * T_ * 3 * H_];   // [B,T,3H]
__device__ float g_att[(size_t)B_ * T_ * H_];       // [B,T,H] attn out (tf32-rounded)
__device__ float g_x[(size_t)B_ * T_ * H_];         // tf32-rounded x
__device__ float g_wqkv[(size_t)H_ * 3 * H_];       // tf32-rounded W_qkv [K,N]
__device__ float g_wout[(size_t)H_ * H_];           // tf32-rounded W_out [K,N]

__device__ __forceinline__ float f2tf32(float x) {
    uint32_t u;
    asm("cvt.rna.tf32.f32 %0, %1;" : "=r"(u) : "f"(x));
    return __uint_as_float(u);
}

__device__ __forceinline__ void mma_tf32(float c[4], const uint32_t a[4], const uint32_t b[2]) {
    asm volatile(
        "mma.sync.aligned.m16n8k8.row.col.f32.tf32.tf32.f32 "
        "{%0,%1,%2,%3}, {%4,%5,%6,%7}, {%8,%9}, {%0,%1,%2,%3};"
        : "+f"(c[0]), "+f"(c[1]), "+f"(c[2]), "+f"(c[3])
        : "r"(a[0]), "r"(a[1]), "r"(a[2]), "r"(a[3]), "r"(b[0]), "r"(b[1]));
}

__device__ __forceinline__ void cp_async16(float* smem_dst, const float* gsrc) {
    uint32_t s = (uint32_t)__cvta_generic_to_shared(smem_dst);
    asm volatile("cp.async.cg.shared.global [%0], [%1], 16;" :: "r"(s), "l"(gsrc));
}
__device__ __forceinline__ void cp_commit() {
    asm volatile("cp.async.commit_group;");
}
template <int N>
__device__ __forceinline__ void cp_wait() {
    asm volatile("cp.async.wait_group %0;" :: "n"(N));
}

// ---------------------------------------------------------------------------
// Prepass: elementwise tf32 rounding (rna) of GEMM operands.
// ---------------------------------------------------------------------------
__global__ void round_tf32_kernel(const float* __restrict__ src,
                                  float* __restrict__ dst, int n4)
{
    const int i = blockIdx.x * blockDim.x + threadIdx.x;
    if (i < n4) {
        float4 v = ((const float4*)src)[i];
        v.x = f2tf32(v.x); v.y = f2tf32(v.y);
        v.z = f2tf32(v.z); v.w = f2tf32(v.w);
        ((float4*)dst)[i] = v;
    }
}

// ---------------------------------------------------------------------------
// TF32 tensor-core GEMM, CUTLASS-shape: CTA 128x256, warp tile 64x64,
// 8 warps (2x4), BK=32, 3-stage cp.async pipeline (ONE syncthreads/chunk),
// register fragment double-buffering across ks-steps.
// Inputs pre-rounded to tf32. C[M,N] = A[M,K] @ Bm[K,N] + bias[N].
// ---------------------------------------------------------------------------
#define BM 128
#define BN 256
#define BK 32
#define NSTAGE 3
#define AS_STRIDE 36
#define BS_STRIDE 264
#define A_FLOATS (BM * AS_STRIDE)                 // 4608
#define B_FLOATS (BK * BS_STRIDE)                 // 8448
#define STAGE_FLOATS (A_FLOATS + B_FLOATS)        // 13056
#define GEMM_SMEM (NSTAGE * STAGE_FLOATS * 4)     // 156672 B

__global__ __launch_bounds__(256, 1)
void gemm_tf32_bias(const float* __restrict__ A, const float* __restrict__ Bm,
                    const float* __restrict__ bias, float* __restrict__ C,
                    int M, int N, int K)
{
    extern __shared__ float smem[];

    const int tid  = threadIdx.x;
    const int wid  = tid >> 5;
    const int lane = tid & 31;
    const int wm   = wid >> 2;          // 0..1 (M dir)
    const int wn   = wid & 3;           // 0..3 (N dir)
    const int grp  = lane >> 2;         // 0..7
    const int qid  = lane & 3;          // 0..3

    const float* Ab = A  + (size_t)(blockIdx.y * BM) * K;
    const float* Bb = Bm + (size_t)(blockIdx.x * BN);

    float acc[4][8][4];
#pragma unroll
    for (int m = 0; m < 4; m++)
#pragma unroll
        for (int n = 0; n < 8; n++)
#pragma unroll
            for (int r = 0; r < 4; r++) acc[m][n][r] = 0.f;

    const int NCH = K / BK;   // 32

    auto load_stage = [&](int k0, int s) {
        float* As = smem + s * STAGE_FLOATS;
        float* Bs = As + A_FLOATS;
#pragma unroll
        for (int i = 0; i < 4; i++) {               // A: 128x32 = 1024 f4
            const int flat = tid + i * 256;
            const int r  = flat >> 3;               // 0..127
            const int c4 = (flat & 7) * 4;          // 0..28
            cp_async16(As + r * AS_STRIDE + c4, Ab + (size_t)r * K + k0 + c4);
        }
#pragma unroll
        for (int i = 0; i < 8; i++) {               // B: 32x256 = 2048 f4
            const int flat = tid + i * 256;
            const int r  = flat >> 6;               // 0..31
            const int c4 = (flat & 63) * 4;         // 0..252
            cp_async16(Bs + r * BS_STRIDE + c4, Bb + (size_t)(k0 + r) * N + c4);
        }
        cp_commit();
    };

    load_stage(0, 0);
    load_stage(BK, 1);

    int stage = 0;
    for (int it = 0; it < NCH; it++) {
        if (it + 1 < NCH) cp_wait<1>(); else cp_wait<0>();
        __syncthreads();    // stage `stage` ready; all warps done reading stage (it-1)%3

        if (it + 2 < NCH) {
            int s2 = stage + 2; if (s2 >= NSTAGE) s2 -= NSTAGE;
            load_stage((it + 2) * BK, s2);
        }

        const float* As = smem + stage * STAGE_FLOATS;
        const float* Bs = As + A_FLOATS;

        // fragment double-buffered ks loop (4 steps of K=8)
        uint32_t af[2][4][4], bf[2][8][2];
#pragma unroll
        for (int m = 0; m < 4; m++) {
            const int r = wm * 64 + m * 16;
            af[0][m][0] = __float_as_uint(As[(r + grp    ) * AS_STRIDE + qid    ]);
            af[0][m][1] = __float_as_uint(As[(r + grp + 8) * AS_STRIDE + qid    ]);
            af[0][m][2] = __float_as_uint(As[(r + grp    ) * AS_STRIDE + qid + 4]);
            af[0][m][3] = __float_as_uint(As[(r + grp + 8) * AS_STRIDE + qid + 4]);
        }
#pragma unroll
        for (int n = 0; n < 8; n++) {
            const int c = wn * 64 + n * 8 + grp;
            bf[0][n][0] = __float_as_uint(Bs[(qid    ) * BS_STRIDE + c]);
            bf[0][n][1] = __float_as_uint(Bs[(qid + 4) * BS_STRIDE + c]);
        }

#pragma unroll
        for (int ks = 0; ks < 4; ks++) {
            const int cur = ks & 1, nxt = cur ^ 1;
            if (ks < 3) {
                const int kb = (ks + 1) * 8;
#pragma unroll
                for (int m = 0; m < 4; m++) {
                    const int r = wm * 64 + m * 16;
                    af[nxt][m][0] = __float_as_uint(As[(r + grp    ) * AS_STRIDE + kb + qid    ]);
                    af[nxt][m][1] = __float_as_uint(As[(r + grp + 8) * AS_STRIDE + kb + qid    ]);
                    af[nxt][m][2] = __float_as_uint(As[(r + grp    ) * AS_STRIDE + kb + qid + 4]);
                    af[nxt][m][3] = __float_as_uint(As[(r + grp + 8) * AS_STRIDE + kb + qid + 4]);
                }
#pragma unroll
                for (int n = 0; n < 8; n++) {
                    const int c = wn * 64 + n * 8 + grp;
                    bf[nxt][n][0] = __float_as_uint(Bs[(kb + qid    ) * BS_STRIDE + c]);
                    bf[nxt][n][1] = __float_as_uint(Bs[(kb + qid + 4) * BS_STRIDE + c]);
                }
            }
#pragma unroll
            for (int m = 0; m < 4; m++)
#pragma unroll
                for (int n = 0; n < 8; n++)
                    mma_tf32(acc[m][n], af[cur][m], bf[cur][n]);
        }

        stage = stage + 1; if (stage >= NSTAGE) stage -= NSTAGE;
    }

    // Epilogue with bias
#pragma unroll
    for (int m = 0; m < 4; m++) {
        const int row0 = blockIdx.y * BM + wm * 64 + m * 16 + grp;
#pragma unroll
        for (int n = 0; n < 8; n++) {
            const int col = blockIdx.x * BN + wn * 64 + n * 8 + qid * 2;
            const float b0 = bias[col], b1 = bias[col + 1];
            float2 v0 = make_float2(acc[m][n][0] + b0, acc[m][n][1] + b1);
            float2 v1 = make_float2(acc[m][n][2] + b0, acc[m][n][3] + b1);
            *(float2*)(C + (size_t)row0 * N + col)       = v0;
            *(float2*)(C + (size_t)(row0 + 8) * N + col) = v1;
        }
    }
}

// ---------------------------------------------------------------------------
// Banded causal attention on tensor cores (tf32 mma, flash online softmax).
// Unchanged (passing, ~58us). Epilogue writes tf32-rounded output.
// ---------------------------------------------------------------------------
#define ATTN_SMEM2 ((64*68*3 + 64*72) * 4)

__global__ __launch_bounds__(128)
void attn_mma_kernel(float* __restrict__ out)
{
    extern __shared__ float sm[];
    float* Qs = sm;                   // [64][68]
    float* Ps = Qs + 64 * 68;         // [64][68]
    float* Ks = Ps + 64 * 68;         // [64][68]
    float* Vs = Ks + 64 * 68;         // [64][72]

    const int qt  = blockIdx.x;
    const int h   = blockIdx.y;
    const int b   = blockIdx.z;
    const int tid = threadIdx.x;
    const int wid  = tid >> 5;
    const int lane = tid & 31;
    const int g = lane >> 2;
    const int q = lane & 3;
    const int r0 = wid * 16;

    const size_t rs = 3 * H_;
    const size_t base_bt = (size_t)b * T_ * rs + (size_t)h * HD_;
    const size_t qbase = base_bt + (size_t)(qt * 64) * rs;

#pragma unroll
    for (int it = 0; it < 8; it++) {
        const int idx = tid + it * 128;
        const int i = idx >> 4, d4 = (idx & 15) << 2;
        float4 v = *(const float4*)&g_qkv[qbase + (size_t)i * rs + d4];
        float4 w;
        w.x = f2tf32(v.x * 0.125f);
        w.y = f2tf32(v.y * 0.125f);
        w.z = f2tf32(v.z * 0.125f);
        w.w = f2tf32(v.w * 0.125f);
        *(float4*)&Qs[i * 68 + d4] = w;
    }

    float oc[8][4];
#pragma unroll
    for (int nt = 0; nt < 8; nt++)
#pragma unroll
        for (int r = 0; r < 4; r++) oc[nt][r] = 0.f;

    float m0 = -1e30f, m1 = -1e30f, l0 = 0.f, l1 = 0.f;

    int kt0 = qt - 4; if (kt0 < 0) kt0 = 0;

    for (int kt = kt0; kt <= qt; kt++) {
        __syncthreads();

        const size_t kbase = base_bt + (size_t)(kt * 64) * rs + H_;
#pragma unroll
        for (int it = 0; it < 8; it++) {
            const int idx = tid + it * 128;
            const int j = idx >> 4, d4 = (idx & 15) << 2;
            float4 kv = *(const float4*)&g_qkv[kbase + (size_t)j * rs + d4];
            float4 vv = *(const float4*)&g_qkv[kbase + H_ + (size_t)j * rs + d4];
            float4 kw, vw;
            kw.x = f2tf32(kv.x); kw.y = f2tf32(kv.y); kw.z = f2tf32(kv.z); kw.w = f2tf32(kv.w);
            vw.x = f2tf32(vv.x); vw.y = f2tf32(vv.y); vw.z = f2tf32(vv.z); vw.w = f2tf32(vv.w);
            *(float4*)&Ks[j * 68 + d4] = kw;
            *(float4*)&Vs[j * 72 + d4] = vw;
        }
        __syncthreads();

        float s[8][4];
#pragma unroll
        for (int nt = 0; nt < 8; nt++)
#pragma unroll
            for (int r = 0; r < 4; r++) s[nt][r] = 0.f;

#pragma unroll
        for (int ks = 0; ks < 8; ks++) {
            const int kb = ks * 8;
            uint32_t a[4];
            a[0] = __float_as_uint(Qs[(r0 + g    ) * 68 + kb + q    ]);
            a[1] = __float_as_uint(Qs[(r0 + g + 8) * 68 + kb + q    ]);
            a[2] = __float_as_uint(Qs[(r0 + g    ) * 68 + kb + q + 4]);
            a[3] = __float_as_uint(Qs[(r0 + g + 8) * 68 + kb + q + 4]);
#pragma unroll
            for (int nt = 0; nt < 8; nt++) {
                uint32_t bb[2];
                bb[0] = __float_as_uint(Ks[(nt * 8 + g) * 68 + kb + q    ]);
                bb[1] = __float_as_uint(Ks[(nt * 8 + g) * 68 + kb + q + 4]);
                mma_tf32(s[nt], a, bb);
            }
        }

        const int ig0 = qt * 64 + r0 + g;
        const int ig1 = ig0 + 8;
#pragma unroll
        for (int nt = 0; nt < 8; nt++) {
            const int jg = kt * 64 + nt * 8 + 2 * q;
            int d00 = ig0 - jg;     if (d00 < 0 || d00 >= WIN_) s[nt][0] = -1e30f;
            int d01 = ig0 - jg - 1; if (d01 < 0 || d01 >= WIN_) s[nt][1] = -1e30f;
            int d10 = ig1 - jg;     if (d10 < 0 || d10 >= WIN_) s[nt][2] = -1e30f;
            int d11 = ig1 - jg - 1; if (d11 < 0 || d11 >= WIN_) s[nt][3] = -1e30f;
        }
        float mx0 = -1e30f, mx1 = -1e30f;
#pragma unroll
        for (int nt = 0; nt < 8; nt++) {
            mx0 = fmaxf(mx0, fmaxf(s[nt][0], s[nt][1]));
            mx1 = fmaxf(mx1, fmaxf(s[nt][2], s[nt][3]));
        }
        mx0 = fmaxf(mx0, __shfl_xor_sync(0xffffffffu, mx0, 1));
        mx0 = fmaxf(mx0, __shfl_xor_sync(0xffffffffu, mx0, 2));
        mx1 = fmaxf(mx1, __shfl_xor_sync(0xffffffffu, mx1, 1));
        mx1 = fmaxf(mx1, __shfl_xor_sync(0xffffffffu, mx1, 2));

        const float mn0 = fmaxf(m0, mx0), mn1 = fmaxf(m1, mx1);
        const float e0 = __expf(m0 - mn0), e1 = __expf(m1 - mn1);
        float rs0 = 0.f, rs1 = 0.f;
#pragma unroll
        for (int nt = 0; nt < 8; nt++) {
            const float p00 = __expf(s[nt][0] - mn0);
            const float p01 = __expf(s[nt][1] - mn0);
            const float p10 = __expf(s[nt][2] - mn1);
            const float p11 = __expf(s[nt][3] - mn1);
            rs0 += p00 + p01;
            rs1 += p10 + p11;
            float2 v0 = make_float2(f2tf32(p00), f2tf32(p01));
            float2 v1 = make_float2(f2tf32(p10), f2tf32(p11));
            *(float2*)&Ps[(r0 + g    ) * 68 + nt * 8 + 2 * q] = v0;
            *(float2*)&Ps[(r0 + g + 8) * 68 + nt * 8 + 2 * q] = v1;
        }
        rs0 += __shfl_xor_sync(0xffffffffu, rs0, 1);
        rs0 += __shfl_xor_sync(0xffffffffu, rs0, 2);
        rs1 += __shfl_xor_sync(0xffffffffu, rs1, 1);
        rs1 += __shfl_xor_sync(0xffffffffu, rs1, 2);

        l0 = l0 * e0 + rs0;  m0 = mn0;
        l1 = l1 * e1 + rs1;  m1 = mn1;

#pragma unroll
        for (int nt = 0; nt < 8; nt++) {
            oc[nt][0] *= e0; oc[nt][1] *= e0;
            oc[nt][2] *= e1; oc[nt][3] *= e1;
        }
        __syncthreads();

#pragma unroll
        for (int ks = 0; ks < 8; ks++) {
            const int kb = ks * 8;
            uint32_t a[4];
            a[0] = __float_as_uint(Ps[(r0 + g    ) * 68 + kb + q    ]);
            a[1] = __float_as_uint(Ps[(r0 + g + 8) * 68 + kb + q    ]);
            a[2] = __float_as_uint(Ps[(r0 + g    ) * 68 + kb + q + 4]);
            a[3] = __float_as_uint(Ps[(r0 + g + 8) * 68 + kb + q + 4]);
#pragma unroll
            for (int nt = 0; nt < 8; nt++) {
                uint32_t bb[2];
                bb[0] = __float_as_uint(Vs[(kb + q    ) * 72 + nt * 8 + g]);
                bb[1] = __float_as_uint(Vs[(kb + q + 4) * 72 + nt * 8 + g]);
                mma_tf32(oc[nt], a, bb);
            }
        }
    }

    const float inv0 = 1.f / l0, inv1 = 1.f / l1;
    const int row0g = qt * 64 + r0 + g;
#pragma unroll
    for (int nt = 0; nt < 8; nt++) {
        const int col = h * HD_ + nt * 8 + 2 * q;
        float2 v0 = make_float2(f2tf32(oc[nt][0] * inv0), f2tf32(oc[nt][1] * inv0));
        float2 v1 = make_float2(f2tf32(oc[nt][2] * inv1), f2tf32(oc[nt][3] * inv1));
        *(float2*)&out[(size_t)(b * T_ + row0g    ) * H_ + col] = v0;
        *(float2*)&out[(size_t)(b * T_ + row0g + 8) * H_ + col] = v1;
    }
}

// ---------------------------------------------------------------------------
// Launch: round prepass -> qkv GEMM -> attention (mma) -> out GEMM
// ---------------------------------------------------------------------------
extern "C" void kernel_launch(void* const* d_in, const int* in_sizes, int n_in,
                              void* d_out, int out_size)
{
    const float* x     = (const float*)d_in[0];
    const float* W_qkv = (const float*)d_in[1];
    const float* b_qkv = (const float*)d_in[2];
    const float* W_out = (const float*)d_in[3];
    const float* b_out = (const float*)d_in[4];
    float* out = (float*)d_out;

    float* qkv;  cudaGetSymbolAddress((void**)&qkv,  g_qkv);
    float* att;  cudaGetSymbolAddress((void**)&att,  g_att);
    float* xr;   cudaGetSymbolAddress((void**)&xr,   g_x);
    float* wq;   cudaGetSymbolAddress((void**)&wq,   g_wqkv);
    float* wo;   cudaGetSymbolAddress((void**)&wo,   g_wout);

    const int M = B_ * T_;

    // 0) tf32 rounding prepass
    {
        const int nx = (B_ * T_ * H_) / 4;
        round_tf32_kernel<<<(nx + 255) / 256, 256>>>(x, xr, nx);
        const int nq = (H_ * 3 * H_) / 4;
        round_tf32_kernel<<<(nq + 255) / 256, 256>>>(W_qkv, wq, nq);
        const int no = (H_ * H_) / 4;
        round_tf32_kernel<<<(no + 255) / 256, 256>>>(W_out, wo, no);
    }

    cudaFuncSetAttribute(gemm_tf32_bias,
                         cudaFuncAttributeMaxDynamicSharedMemorySize, GEMM_SMEM);
    // 1) QKV projection: [4096,1024] @ [1024,3072] + bias
    {
        dim3 grid((3 * H_) / BN, M / BM);     // (12, 32)
        gemm_tf32_bias<<<grid, 256, GEMM_SMEM>>>(xr, wq, b_qkv, qkv, M, 3 * H_, H_);
    }
    // 2) Banded attention
    {
        cudaFuncSetAttribute(attn_mma_kernel,
                             cudaFuncAttributeMaxDynamicSharedMemorySize, ATTN_SMEM2);
        dim3 grid(T_ / 64, NH_, B_);
        attn_mma_kernel<<<grid, 128, ATTN_SMEM2>>>(att);
    }
    // 3) Output projection: [4096,1024] @ [1024,1024] + bias
    {
        dim3 grid(H_ / BN, M / BM);           // (4, 32)
        gemm_tf32_bias<<<grid, 256, GEMM_SMEM>>>(att, wo, b_out, out, M, H_, H_);
    }
}

// round 12
// speedup vs baseline: 1.1059x; 1.0776x over previous
#include <cuda_runtime.h>
#include <math.h>
#include <stdint.h>

// Problem constants
#define B_    2
#define T_    2048
#define H_    1024
#define NH_   16
#define HD_   64
#define WIN_  256

// Scratch (device globals — allocation-free per harness rules)
__device__ float g_qkv[(size_t)B_ * T_ * 3 * H_];    // [B,T,3H]
__device__ float g_att[(size_t)B_ * T_ * H_];        // attn out, normal layout
__device__ float g_xp[(size_t)B_ * T_ * H_];         // x, fragment-permuted
__device__ float g_attp[(size_t)B_ * T_ * H_];       // attn out, fragment-permuted
__device__ float g_wqkvp[(size_t)H_ * 3 * H_];       // W_qkv, fragment-permuted
__device__ float g_woutp[(size_t)H_ * H_];           // W_out, fragment-permuted

__device__ __forceinline__ float f2tf32(float x) {
    uint32_t u;
    asm("cvt.rna.tf32.f32 %0, %1;" : "=r"(u) : "f"(x));
    return __uint_as_float(u);
}

__device__ __forceinline__ void mma_tf32(float c[4], const uint32_t a[4], const uint32_t b[2]) {
    asm volatile(
        "mma.sync.aligned.m16n8k8.row.col.f32.tf32.tf32.f32 "
        "{%0,%1,%2,%3}, {%4,%5,%6,%7}, {%8,%9}, {%0,%1,%2,%3};"
        : "+f"(c[0]), "+f"(c[1]), "+f"(c[2]), "+f"(c[3])
        : "r"(a[0]), "r"(a[1]), "r"(a[2]), "r"(a[3]), "r"(b[0]), "r"(b[1]));
}

__device__ __forceinline__ void cp_async16(void* smem_dst, const void* gsrc) {
    uint32_t s = (uint32_t)__cvta_generic_to_shared(smem_dst);
    asm volatile("cp.async.cg.shared.global [%0], [%1], 16;" :: "r"(s), "l"(gsrc));
}
__device__ __forceinline__ void cp_commit() {
    asm volatile("cp.async.commit_group;");
}
template <int N>
__device__ __forceinline__ void cp_wait() {
    asm volatile("cp.async.wait_group %0;" :: "n"(N));
}

// ---------------------------------------------------------------------------
// Repack A: src [M][K] row-major fp32 -> dst fragment-permuted + tf32-rounded.
// dst 16B chunk idx = (mt*(K/8) + kt)*32 + lane, lane=(grp<<2)|qid, holds:
//   { A[mt*16+grp][kt*8+qid], A[mt*16+grp+8][kt*8+qid],
//     A[mt*16+grp][kt*8+qid+4], A[mt*16+grp+8][kt*8+qid+4] }
// (= the m16n8k8 tf32 A fragment of that thread)
// ---------------------------------------------------------------------------
__global__ void repack_a_kernel(const float* __restrict__ src,
                                float* __restrict__ dst, int M, int K)
{
    const int idx = blockIdx.x * blockDim.x + threadIdx.x;
    const int total = (M >> 4) * (K >> 3) * 32;
    if (idx >= total) return;
    const int lane = idx & 31;
    const int kt   = (idx >> 5) % (K >> 3);
    const int mt   = idx / (32 * (K >> 3));
    const int grp = lane >> 2, qid = lane & 3;
    const int r0 = mt * 16 + grp, c0 = kt * 8 + qid;
    float4 v;
    v.x = f2tf32(src[(size_t)r0 * K + c0]);
    v.y = f2tf32(src[(size_t)(r0 + 8) * K + c0]);
    v.z = f2tf32(src[(size_t)r0 * K + c0 + 4]);
    v.w = f2tf32(src[(size_t)(r0 + 8) * K + c0 + 4]);
    ((float4*)dst)[idx] = v;
}

// ---------------------------------------------------------------------------
// Repack B: src [K][N] row-major fp32 -> fragment-permuted + tf32-rounded.
// dst 16B chunk idx = (nt*(K/16) + kp)*32 + lane, c = nt*8+grp, holds:
//   { B[kp*16+qid][c], B[kp*16+qid+4][c], B[kp*16+8+qid][c], B[kp*16+12+qid][c] }
// (elements 0,1 = B fragment for ks=2kp; elements 2,3 = ks=2kp+1)
// ---------------------------------------------------------------------------
__global__ void repack_b_kernel(const float* __restrict__ src,
                                float* __restrict__ dst, int K, int N)
{
    const int idx = blockIdx.x * blockDim.x + threadIdx.x;
    const int total = (N >> 3) * (K >> 4) * 32;
    if (idx >= total) return;
    const int lane = idx & 31;
    const int kp   = (idx >> 5) % (K >> 4);
    const int nt   = idx / (32 * (K >> 4));
    const int grp = lane >> 2, qid = lane & 3;
    const int c = nt * 8 + grp, r = kp * 16;
    float4 v;
    v.x = f2tf32(src[(size_t)(r + qid     ) * N + c]);
    v.y = f2tf32(src[(size_t)(r + qid +  4) * N + c]);
    v.z = f2tf32(src[(size_t)(r + qid +  8) * N + c]);
    v.w = f2tf32(src[(size_t)(r + qid + 12) * N + c]);
    ((float4*)dst)[idx] = v;
}

// ---------------------------------------------------------------------------
// TF32 tensor-core GEMM on fragment-permuted operands.
// CTA 128x256, 8 warps (2x4), warp tile 64x64, BK=32, 3-stage cp.async.
// Fragment loads are LDS.128 (16 A + 16 B per warp per chunk).
// C[M,N] = A[M,K] @ B[K,N] + bias[N], C row-major normal layout.
// ---------------------------------------------------------------------------
#define BM 128
#define BN 256
#define BK 32
#define NSTAGE 3
#define A_STAGE_BYTES (8 * 4 * 32 * 16)     // mloc x ktloc x lane x 16B = 16384
#define B_STAGE_BYTES (32 * 2 * 32 * 16)    // ntloc x kploc x lane x 16B = 32768
#define STAGE_BYTES   (A_STAGE_BYTES + B_STAGE_BYTES)   // 49152
#define GEMM_SMEM     (NSTAGE * STAGE_BYTES)            // 147456

__global__ __launch_bounds__(256, 1)
void gemm_tf32_bias(const float* __restrict__ Ap, const float* __restrict__ Bp,
                    const float* __restrict__ bias, float* __restrict__ C,
                    int M, int N, int K)
{
    extern __shared__ char smem[];

    const int tid  = threadIdx.x;
    const int wid  = tid >> 5;
    const int lane = tid & 31;
    const int wm   = wid >> 2;          // 0..1 (M dir)
    const int wn   = wid & 3;           // 0..3 (N dir)
    const int grp  = lane >> 2;
    const int qid  = lane & 3;
    const int bx = blockIdx.x, by = blockIdx.y;

    const int KT = K >> 3;              // k8-tiles
    const int KP = K >> 4;              // k16-pairs

    float acc[4][8][4];
#pragma unroll
    for (int m = 0; m < 4; m++)
#pragma unroll
        for (int n = 0; n < 8; n++)
#pragma unroll
            for (int r = 0; r < 4; r++) acc[m][n][r] = 0.f;

    const int NCH = K / BK;   // 32

    auto load_stage = [&](int it, int s) {
        char* As = smem + s * STAGE_BYTES;
        char* Bs = As + A_STAGE_BYTES;
        // A: 1024 x 16B chunks, layout [mloc(8)][ktloc(4)][lane(32)]
#pragma unroll
        for (int i = 0; i < 4; i++) {
            const int f = tid + i * 256;
            const int mloc = f >> 7;
            const int rest = f & 127;       // ktloc*32 + lane
            const size_t srcidx = ((size_t)(by * 8 + mloc) * KT + it * 4) * 32 + rest;
            cp_async16(As + f * 16, Ap + srcidx * 4);
        }
        // B: 2048 x 16B chunks, layout [ntloc(32)][kploc(2)][lane(32)]
#pragma unroll
        for (int i = 0; i < 8; i++) {
            const int f = tid + i * 256;
            const int ntloc = f >> 6;
            const int rest = f & 63;        // kploc*32 + lane
            const size_t srcidx = ((size_t)(bx * 32 + ntloc) * KP + it * 2) * 32 + rest;
            cp_async16(Bs + f * 16, Bp + srcidx * 4);
        }
        cp_commit();
    };

    load_stage(0, 0);
    load_stage(1, 1);

    int stage = 0;
    for (int it = 0; it < NCH; it++) {
        if (it + 1 < NCH) cp_wait<1>(); else cp_wait<0>();
        __syncthreads();

        if (it + 2 < NCH) {
            int s2 = stage + 2; if (s2 >= NSTAGE) s2 -= NSTAGE;
            load_stage(it + 2, s2);
        }

        const char* As = smem + stage * STAGE_BYTES;
        const char* Bs = As + A_STAGE_BYTES;

#pragma unroll
        for (int kp = 0; kp < 2; kp++) {
            uint4 bfrag[8];
#pragma unroll
            for (int n = 0; n < 8; n++)
                bfrag[n] = *(const uint4*)(Bs + ((((wn * 8 + n) * 2 + kp) * 32 + lane) << 4));
#pragma unroll
            for (int half = 0; half < 2; half++) {
                uint4 afrag[4];
#pragma unroll
                for (int m = 0; m < 4; m++)
                    afrag[m] = *(const uint4*)(As + ((((wm * 4 + m) * 4 + kp * 2 + half) * 32 + lane) << 4));
#pragma unroll
                for (int m = 0; m < 4; m++) {
                    const uint32_t a[4] = {afrag[m].x, afrag[m].y, afrag[m].z, afrag[m].w};
#pragma unroll
                    for (int n = 0; n < 8; n++) {
                        const uint32_t b[2] = {half ? bfrag[n].z : bfrag[n].x,
                                               half ? bfrag[n].w : bfrag[n].y};
                        mma_tf32(acc[m][n], a, b);
                    }
                }
            }
        }

        stage = stage + 1; if (stage >= NSTAGE) stage -= NSTAGE;
    }

    // Epilogue with bias (normal row-major C)
#pragma unroll
    for (int m = 0; m < 4; m++) {
        const int row0 = by * BM + wm * 64 + m * 16 + grp;
#pragma unroll
        for (int n = 0; n < 8; n++) {
            const int col = bx * BN + wn * 64 + n * 8 + qid * 2;
            const float b0 = bias[col], b1 = bias[col + 1];
            float2 v0 = make_float2(acc[m][n][0] + b0, acc[m][n][1] + b1);
            float2 v1 = make_float2(acc[m][n][2] + b0, acc[m][n][3] + b1);
            *(float2*)(C + (size_t)row0 * N + col)       = v0;
            *(float2*)(C + (size_t)(row0 + 8) * N + col) = v1;
        }
    }
}

// ---------------------------------------------------------------------------
// Banded causal attention on tensor cores (tf32 mma, flash online softmax).
// Unchanged (passing, ~58us). Writes g_att in normal layout, tf32-rounded.
// ---------------------------------------------------------------------------
#define ATTN_SMEM2 ((64*68*3 + 64*72) * 4)

__global__ __launch_bounds__(128)
void attn_mma_kernel(float* __restrict__ out)
{
    extern __shared__ float sm[];
    float* Qs = sm;                   // [64][68]
    float* Ps = Qs + 64 * 68;         // [64][68]
    float* Ks = Ps + 64 * 68;         // [64][68]
    float* Vs = Ks + 64 * 68;         // [64][72]

    const int qt  = blockIdx.x;
    const int h   = blockIdx.y;
    const int b   = blockIdx.z;
    const int tid = threadIdx.x;
    const int wid  = tid >> 5;
    const int lane = tid & 31;
    const int g = lane >> 2;
    const int q = lane & 3;
    const int r0 = wid * 16;

    const size_t rs = 3 * H_;
    const size_t base_bt = (size_t)b * T_ * rs + (size_t)h * HD_;
    const size_t qbase = base_bt + (size_t)(qt * 64) * rs;

#pragma unroll
    for (int it = 0; it < 8; it++) {
        const int idx = tid + it * 128;
        const int i = idx >> 4, d4 = (idx & 15) << 2;
        float4 v = *(const float4*)&g_qkv[qbase + (size_t)i * rs + d4];
        float4 w;
        w.x = f2tf32(v.x * 0.125f);
        w.y = f2tf32(v.y * 0.125f);
        w.z = f2tf32(v.z * 0.125f);
        w.w = f2tf32(v.w * 0.125f);
        *(float4*)&Qs[i * 68 + d4] = w;
    }

    float oc[8][4];
#pragma unroll
    for (int nt = 0; nt < 8; nt++)
#pragma unroll
        for (int r = 0; r < 4; r++) oc[nt][r] = 0.f;

    float m0 = -1e30f, m1 = -1e30f, l0 = 0.f, l1 = 0.f;

    int kt0 = qt - 4; if (kt0 < 0) kt0 = 0;

    for (int kt = kt0; kt <= qt; kt++) {
        __syncthreads();

        const size_t kbase = base_bt + (size_t)(kt * 64) * rs + H_;
#pragma unroll
        for (int it = 0; it < 8; it++) {
            const int idx = tid + it * 128;
            const int j = idx >> 4, d4 = (idx & 15) << 2;
            float4 kv = *(const float4*)&g_qkv[kbase + (size_t)j * rs + d4];
            float4 vv = *(const float4*)&g_qkv[kbase + H_ + (size_t)j * rs + d4];
            float4 kw, vw;
            kw.x = f2tf32(kv.x); kw.y = f2tf32(kv.y); kw.z = f2tf32(kv.z); kw.w = f2tf32(kv.w);
            vw.x = f2tf32(vv.x); vw.y = f2tf32(vv.y); vw.z = f2tf32(vv.z); vw.w = f2tf32(vv.w);
            *(float4*)&Ks[j * 68 + d4] = kw;
            *(float4*)&Vs[j * 72 + d4] = vw;
        }
        __syncthreads();

        float s[8][4];
#pragma unroll
        for (int nt = 0; nt < 8; nt++)
#pragma unroll
            for (int r = 0; r < 4; r++) s[nt][r] = 0.f;

#pragma unroll
        for (int ks = 0; ks < 8; ks++) {
            const int kb = ks * 8;
            uint32_t a[4];
            a[0] = __float_as_uint(Qs[(r0 + g    ) * 68 + kb + q    ]);
            a[1] = __float_as_uint(Qs[(r0 + g + 8) * 68 + kb + q    ]);
            a[2] = __float_as_uint(Qs[(r0 + g    ) * 68 + kb + q + 4]);
            a[3] = __float_as_uint(Qs[(r0 + g + 8) * 68 + kb + q + 4]);
#pragma unroll
            for (int nt = 0; nt < 8; nt++) {
                uint32_t bb[2];
                bb[0] = __float_as_uint(Ks[(nt * 8 + g) * 68 + kb + q    ]);
                bb[1] = __float_as_uint(Ks[(nt * 8 + g) * 68 + kb + q + 4]);
                mma_tf32(s[nt], a, bb);
            }
        }

        const int ig0 = qt * 64 + r0 + g;
        const int ig1 = ig0 + 8;
#pragma unroll
        for (int nt = 0; nt < 8; nt++) {
            const int jg = kt * 64 + nt * 8 + 2 * q;
            int d00 = ig0 - jg;     if (d00 < 0 || d00 >= WIN_) s[nt][0] = -1e30f;
            int d01 = ig0 - jg - 1; if (d01 < 0 || d01 >= WIN_) s[nt][1] = -1e30f;
            int d10 = ig1 - jg;     if (d10 < 0 || d10 >= WIN_) s[nt][2] = -1e30f;
            int d11 = ig1 - jg - 1; if (d11 < 0 || d11 >= WIN_) s[nt][3] = -1e30f;
        }
        float mx0 = -1e30f, mx1 = -1e30f;
#pragma unroll
        for (int nt = 0; nt < 8; nt++) {
            mx0 = fmaxf(mx0, fmaxf(s[nt][0], s[nt][1]));
            mx1 = fmaxf(mx1, fmaxf(s[nt][2], s[nt][3]));
        }
        mx0 = fmaxf(mx0, __shfl_xor_sync(0xffffffffu, mx0, 1));
        mx0 = fmaxf(mx0, __shfl_xor_sync(0xffffffffu, mx0, 2));
        mx1 = fmaxf(mx1, __shfl_xor_sync(0xffffffffu, mx1, 1));
        mx1 = fmaxf(mx1, __shfl_xor_sync(0xffffffffu, mx1, 2));

        const float mn0 = fmaxf(m0, mx0), mn1 = fmaxf(m1, mx1);
        const float e0 = __expf(m0 - mn0), e1 = __expf(m1 - mn1);
        float rs0 = 0.f, rs1 = 0.f;
#pragma unroll
        for (int nt = 0; nt < 8; nt++) {
            const float p00 = __expf(s[nt][0] - mn0);
            const float p01 = __expf(s[nt][1] - mn0);
            const float p10 = __expf(s[nt][2] - mn1);
            const float p11 = __expf(s[nt][3] - mn1);
            rs0 += p00 + p01;
            rs1 += p10 + p11;
            float2 v0 = make_float2(f2tf32(p00), f2tf32(p01));
            float2 v1 = make_float2(f2tf32(p10), f2tf32(p11));
            *(float2*)&Ps[(r0 + g    ) * 68 + nt * 8 + 2 * q] = v0;
            *(float2*)&Ps[(r0 + g + 8) * 68 + nt * 8 + 2 * q] = v1;
        }
        rs0 += __shfl_xor_sync(0xffffffffu, rs0, 1);
        rs0 += __shfl_xor_sync(0xffffffffu, rs0, 2);
        rs1 += __shfl_xor_sync(0xffffffffu, rs1, 1);
        rs1 += __shfl_xor_sync(0xffffffffu, rs1, 2);

        l0 = l0 * e0 + rs0;  m0 = mn0;
        l1 = l1 * e1 + rs1;  m1 = mn1;

#pragma unroll
        for (int nt = 0; nt < 8; nt++) {
            oc[nt][0] *= e0; oc[nt][1] *= e0;
            oc[nt][2] *= e1; oc[nt][3] *= e1;
        }
        __syncthreads();

#pragma unroll
        for (int ks = 0; ks < 8; ks++) {
            const int kb = ks * 8;
            uint32_t a[4];
            a[0] = __float_as_uint(Ps[(r0 + g    ) * 68 + kb + q    ]);
            a[1] = __float_as_uint(Ps[(r0 + g + 8) * 68 + kb + q    ]);
            a[2] = __float_as_uint(Ps[(r0 + g    ) * 68 + kb + q + 4]);
            a[3] = __float_as_uint(Ps[(r0 + g + 8) * 68 + kb + q + 4]);
#pragma unroll
            for (int nt = 0; nt < 8; nt++) {
                uint32_t bb[2];
                bb[0] = __float_as_uint(Vs[(kb + q    ) * 72 + nt * 8 + g]);
                bb[1] = __float_as_uint(Vs[(kb + q + 4) * 72 + nt * 8 + g]);
                mma_tf32(oc[nt], a, bb);
            }
        }
    }

    const float inv0 = 1.f / l0, inv1 = 1.f / l1;
    const int row0g = qt * 64 + r0 + g;
#pragma unroll
    for (int nt = 0; nt < 8; nt++) {
        const int col = h * HD_ + nt * 8 + 2 * q;
        float2 v0 = make_float2(f2tf32(oc[nt][0] * inv0), f2tf32(oc[nt][1] * inv0));
        float2 v1 = make_float2(f2tf32(oc[nt][2] * inv1), f2tf32(oc[nt][3] * inv1));
        *(float2*)&out[(size_t)(b * T_ + row0g    ) * H_ + col] = v0;
        *(float2*)&out[(size_t)(b * T_ + row0g + 8) * H_ + col] = v1;
    }
}

// ---------------------------------------------------------------------------
// Launch: repack(x, W) -> QKV GEMM -> attention -> repack(att) -> out GEMM
// ---------------------------------------------------------------------------
extern "C" void kernel_launch(void* const* d_in, const int* in_sizes, int n_in,
                              void* d_out, int out_size)
{
    const float* x     = (const float*)d_in[0];
    const float* W_qkv = (const float*)d_in[1];
    const float* b_qkv = (const float*)d_in[2];
    const float* W_out = (const float*)d_in[3];
    const float* b_out = (const float*)d_in[4];
    float* out = (float*)d_out;

    float* qkv;  cudaGetSymbolAddress((void**)&qkv,  g_qkv);
    float* att;  cudaGetSymbolAddress((void**)&att,  g_att);
    float* xp;   cudaGetSymbolAddress((void**)&xp,   g_xp);
    float* attp; cudaGetSymbolAddress((void**)&attp, g_attp);
    float* wqp;  cudaGetSymbolAddress((void**)&wqp,  g_wqkvp);
    float* wop;  cudaGetSymbolAddress((void**)&wop,  g_woutp);

    const int M = B_ * T_;   // 4096

    // 0) repack + tf32-round operands into fragment order
    {
        const int na = (M / 16) * (H_ / 8) * 32;            // x: 1M chunks
        repack_a_kernel<<<(na + 255) / 256, 256>>>(x, xp, M, H_);
        const int nbq = ((3 * H_) / 8) * (H_ / 16) * 32;    // W_qkv
        repack_b_kernel<<<(nbq + 255) / 256, 256>>>(W_qkv, wqp, H_, 3 * H_);
        const int nbo = (H_ / 8) * (H_ / 16) * 32;          // W_out
        repack_b_kernel<<<(nbo + 255) / 256, 256>>>(W_out, wop, H_, H_);
    }

    cudaFuncSetAttribute(gemm_tf32_bias,
                         cudaFuncAttributeMaxDynamicSharedMemorySize, GEMM_SMEM);

    // 1) QKV projection: [4096,1024] @ [1024,3072] + bias
    {
        dim3 grid((3 * H_) / BN, M / BM);     // (12, 32)
        gemm_tf32_bias<<<grid, 256, GEMM_SMEM>>>(xp, wqp, b_qkv, qkv, M, 3 * H_, H_);
    }

    // 2) Banded attention
    {
        cudaFuncSetAttribute(attn_mma_kernel,
                             cudaFuncAttributeMaxDynamicSharedMemorySize, ATTN_SMEM2);
        dim3 grid(T_ / 64, NH_, B_);
        attn_mma_kernel<<<grid, 128, ATTN_SMEM2>>>(att);
    }

    // 2.5) repack attention output for GEMM2 A operand
    {
        const int na = (M / 16) * (H_ / 8) * 32;
        repack_a_kernel<<<(na + 255) / 256, 256>>>(att, attp, M, H_);
    }

    // 3) Output projection: [4096,1024] @ [1024,1024] + bias
    {
        dim3 grid(H_ / BN, M / BM);           // (4, 32)
        gemm_tf32_bias<<<grid, 256, GEMM_SMEM>>>(attp, wop, b_out, out, M, H_, H_);
    }
}